// round 5
// baseline (speedup 1.0000x reference)
#include <cuda_runtime.h>
#include <cuda_fp16.h>
#include <stdint.h>

#define NUM_USERS 100000
#define NUM_ITEMS 50000
#define N_NODES   (NUM_USERS + NUM_ITEMS)   // 150000
#define EMBED_DIM 64
#define N_EDGES   1000000

#define SCAN_BS   1024
#define N_SCAN_BLOCKS ((N_NODES + SCAN_BS - 1) / SCAN_BS)   // 147

// ---- static device scratch (no allocation allowed) ----
__device__ int     g_deg[N_NODES];
__device__ float   g_dinv[N_NODES];
__device__ int     g_off[N_NODES + 1];
__device__ int     g_cur[N_NODES];
__device__ int     g_bsum[N_SCAN_BLOCKS];
__device__ int2    g_csr[N_EDGES];                 // {src, norm_bits}
__device__ __half2 g_h0[N_NODES * 32];             // fp16 emb
__device__ __half2 g_h1[N_NODES * 32];             // fp16 layer1
__device__ __half2 g_h2[N_NODES * 32];             // fp16 layer2

// -------------------- setup kernels --------------------

__global__ void k_init_counts() {
    int i = blockIdx.x * blockDim.x + threadIdx.x;
    if (i < N_NODES) { g_deg[i] = 0; g_cur[i] = 0; }
}

__global__ void k_degree(const int* __restrict__ edge_index) {
    int e = blockIdx.x * blockDim.x + threadIdx.x;
    if (e < N_EDGES) atomicAdd(&g_deg[edge_index[N_EDGES + e]], 1);
}

// per-block exclusive scan of degrees; also emits dinv (fused, deg already loaded)
__global__ void k_scan_blocks() {
    __shared__ int s[SCAN_BS];
    int tid = threadIdx.x;
    int i = blockIdx.x * SCAN_BS + tid;
    int v = (i < N_NODES) ? g_deg[i] : 0;
    if (i < N_NODES) g_dinv[i] = (v > 0) ? rsqrtf((float)v) : 0.0f;
    s[tid] = v;
    __syncthreads();
    #pragma unroll
    for (int d = 1; d < SCAN_BS; d <<= 1) {
        int t = (tid >= d) ? s[tid - d] : 0;
        __syncthreads();
        s[tid] += t;
        __syncthreads();
    }
    if (i < N_NODES) g_off[i] = s[tid] - v;   // exclusive
    if (tid == SCAN_BS - 1) g_bsum[blockIdx.x] = s[tid];
}

// single-warp shfl scan of the 147 block sums (no serial dependent-load chain)
__global__ void k_scan_aux() {
    const int CH = (N_SCAN_BLOCKS + 31) / 32;   // 5
    int lane = threadIdx.x;
    int base = lane * CH;
    int vals[CH];
    int tot = 0;
    #pragma unroll
    for (int j = 0; j < CH; j++) {
        int idx = base + j;
        int v = (idx < N_SCAN_BLOCKS) ? g_bsum[idx] : 0;
        vals[j] = tot;                          // local exclusive prefix
        tot += v;
    }
    int run = tot;
    #pragma unroll
    for (int d = 1; d < 32; d <<= 1) {
        int t = __shfl_up_sync(0xffffffffu, run, d);
        if (lane >= d) run += t;
    }
    int excl = run - tot;                       // exclusive prefix of lane totals
    #pragma unroll
    for (int j = 0; j < CH; j++) {
        int idx = base + j;
        if (idx < N_SCAN_BLOCKS) g_bsum[idx] = excl + vals[j];
    }
}

__global__ void k_scan_add() {
    int i = blockIdx.x * blockDim.x + threadIdx.x;
    if (i < N_NODES) g_off[i] += g_bsum[i >> 10];
    if (i == 0) g_off[N_NODES] = N_EDGES;
}

// scatter edges into CSR-by-dst, packed {src, norm}
__global__ void k_scatter(const int* __restrict__ edge_index) {
    int e = blockIdx.x * blockDim.x + threadIdx.x;
    if (e < N_EDGES) {
        int src = edge_index[e];
        int dst = edge_index[N_EDGES + e];
        int pos = g_off[dst] + atomicAdd(&g_cur[dst], 1);
        float norm = g_dinv[src] * g_dinv[dst];
        g_csr[pos] = make_int2(src, __float_as_int(norm));
    }
}

// convert fp32 emb -> fp16 (half2 per thread)
__global__ void k_to_half(const float2* __restrict__ emb) {
    int i = blockIdx.x * blockDim.x + threadIdx.x;
    if (i < N_NODES * 32) {
        float2 v = emb[i];
        g_h0[i] = __float22half2_rn(v);
    }
}

// -------------------- propagation --------------------
// one warp per node; lane owns half2 (2 dims), 32 lanes = 64 dims.
// fp16 gathers (128 B/edge), fp32 accumulation. Unrolled x4.
__device__ __forceinline__ float2 gather_node(const __half2* __restrict__ xin,
                                              int beg, int end, int lane) {
    float2 sum = make_float2(0.0f, 0.0f);
    int e = beg;
    for (; e + 3 < end; e += 4) {
        int2 p0 = g_csr[e];
        int2 p1 = g_csr[e + 1];
        int2 p2 = g_csr[e + 2];
        int2 p3 = g_csr[e + 3];
        float2 v0 = __half22float2(xin[(size_t)p0.x * 32 + lane]);
        float2 v1 = __half22float2(xin[(size_t)p1.x * 32 + lane]);
        float2 v2 = __half22float2(xin[(size_t)p2.x * 32 + lane]);
        float2 v3 = __half22float2(xin[(size_t)p3.x * 32 + lane]);
        float w0 = __int_as_float(p0.y), w1 = __int_as_float(p1.y);
        float w2 = __int_as_float(p2.y), w3 = __int_as_float(p3.y);
        sum.x = fmaf(v0.x, w0, sum.x);  sum.y = fmaf(v0.y, w0, sum.y);
        sum.x = fmaf(v1.x, w1, sum.x);  sum.y = fmaf(v1.y, w1, sum.y);
        sum.x = fmaf(v2.x, w2, sum.x);  sum.y = fmaf(v2.y, w2, sum.y);
        sum.x = fmaf(v3.x, w3, sum.x);  sum.y = fmaf(v3.y, w3, sum.y);
    }
    for (; e < end; e++) {
        int2 p = g_csr[e];
        float2 v = __half22float2(xin[(size_t)p.x * 32 + lane]);
        float w = __int_as_float(p.y);
        sum.x = fmaf(v.x, w, sum.x);
        sum.y = fmaf(v.y, w, sum.y);
    }
    return sum;
}

// layer 1: g_h1 = A~ * h0
__global__ void __launch_bounds__(256) k_prop1() {
    int gtid = blockIdx.x * blockDim.x + threadIdx.x;
    int node = gtid >> 5, lane = gtid & 31;
    if (node >= N_NODES) return;
    float2 sum = gather_node(g_h0, g_off[node], g_off[node + 1], lane);
    g_h1[(size_t)node * 32 + lane] = __float22half2_rn(sum);
}

// layer 2: g_h2 = A~ * h1
__global__ void __launch_bounds__(256) k_prop2() {
    int gtid = blockIdx.x * blockDim.x + threadIdx.x;
    int node = gtid >> 5, lane = gtid & 31;
    if (node >= N_NODES) return;
    float2 sum = gather_node(g_h1, g_off[node], g_off[node + 1], lane);
    g_h2[(size_t)node * 32 + lane] = __float22half2_rn(sum);
}

// layer 3 + epilogue: out = 0.25*(emb_fp32 + h1 + h2 + A~*h2)
__global__ void __launch_bounds__(256) k_prop_last(const float2* __restrict__ emb,
                                                   float2* __restrict__ out) {
    int gtid = blockIdx.x * blockDim.x + threadIdx.x;
    int node = gtid >> 5, lane = gtid & 31;
    if (node >= N_NODES) return;

    float2 sum = gather_node(g_h2, g_off[node], g_off[node + 1], lane);

    size_t oi = (size_t)node * 32 + lane;
    float2 e0 = emb[oi];
    float2 a1 = __half22float2(g_h1[oi]);
    float2 a2 = __half22float2(g_h2[oi]);
    float2 o;
    o.x = 0.25f * (e0.x + a1.x + a2.x + sum.x);
    o.y = 0.25f * (e0.y + a1.y + a2.y + sum.y);
    out[oi] = o;
}

// -------------------- launch --------------------

extern "C" void kernel_launch(void* const* d_in, const int* in_sizes, int n_in,
                              void* d_out, int out_size) {
    const int*   edge_index = (const int*)d_in[0];     // int32
    const float* emb_weight = (const float*)d_in[1];
    float*       out        = (float*)d_out;

    const int BS = 256;
    int gn = (N_NODES + BS - 1) / BS;
    int ge = (N_EDGES + BS - 1) / BS;

    k_init_counts<<<gn, BS>>>();
    k_degree<<<ge, BS>>>(edge_index);
    k_scan_blocks<<<N_SCAN_BLOCKS, SCAN_BS>>>();   // also emits dinv
    k_scan_aux<<<1, 32>>>();
    k_scan_add<<<gn, BS>>>();
    k_scatter<<<ge, BS>>>(edge_index);

    int gh = (N_NODES * 32 + BS - 1) / BS;
    k_to_half<<<gh, BS>>>((const float2*)emb_weight);

    int gp = (N_NODES * 32 + BS - 1) / BS;
    k_prop1<<<gp, BS>>>();
    k_prop2<<<gp, BS>>>();
    k_prop_last<<<gp, BS>>>((const float2*)emb_weight, (float2*)out);
}